// round 7
// baseline (speedup 1.0000x reference)
#include <cuda_runtime.h>
#include <math.h>
#include <stdint.h>

// Problem constants (fixed by the reference)
#define NW      65536
#define TPB     128
#define PPB     256                // walker pairs per block (2 chains/thread)
#define NBLK    128                // 32768 pairs / 256; divides 2^32
#define TOTALS  512
#define WARM    128
#define NSTEPS  384
#define CH      8                  // steps per chunk
#define NCH     (TOTALS / CH)      // 64
#define WARM_CH (WARM / CH)        // 16
#define ROWB    ((size_t)NW * 4)   // gmem bytes per step-row
// smem ring (ull units): stage = [N: CH*PPB][U: CH*PPB]
#define UOFF    (CH * PPB)         // 2048 ull
#define STG     (2 * CH * PPB)     // 4096 ull = 32 KB
#define SMEM_BYTES (4 * STG * 8)   // 128 KB

typedef unsigned long long ull;

__device__ float        g_part[8][NBLK];
__device__ unsigned int g_ctr = 0;

// ---------- f32x2 packed helpers ----------
__device__ __forceinline__ ull PKF(float a, float b) {
    ull v; asm("mov.b64 %0, {%1, %2};" : "=l"(v)
               : "r"(__float_as_uint(a)), "r"(__float_as_uint(b)));
    return v;
}
__device__ __forceinline__ ull PKU(unsigned a, unsigned b) {
    ull v; asm("mov.b64 %0, {%1, %2};" : "=l"(v) : "r"(a), "r"(b));
    return v;
}
__device__ __forceinline__ float LO(ull v) { return __uint_as_float((unsigned)v); }
__device__ __forceinline__ float HI(ull v) { return __uint_as_float((unsigned)(v >> 32)); }
__device__ __forceinline__ ull FMA2(ull a, ull b, ull c) {
    ull d; asm("fma.rn.f32x2 %0, %1, %2, %3;" : "=l"(d) : "l"(a), "l"(b), "l"(c));
    return d;
}
__device__ __forceinline__ ull MUL2(ull a, ull b) {
    ull d; asm("mul.rn.f32x2 %0, %1, %2;" : "=l"(d) : "l"(a), "l"(b));
    return d;
}
__device__ __forceinline__ ull ADD2(ull a, ull b) {
    ull d; asm("add.rn.f32x2 %0, %1, %2;" : "=l"(d) : "l"(a), "l"(b));
    return d;
}
__device__ __forceinline__ ull SPL(float a) { return PKF(a, a); }

__device__ __forceinline__ void cp16(uint32_t dst, const void* src) {
    asm volatile("cp.async.cg.shared.global [%0], [%1], 16;" :: "r"(dst), "l"(src));
}

__global__ void __launch_bounds__(TPB) vmc_kernel(
    const float* __restrict__ theta,
    const float* __restrict__ r0,
    const float* __restrict__ sdevp,
    const float* __restrict__ noise,
    const float* __restrict__ unif,
    float* __restrict__ out, int out_size)
{
    extern __shared__ ull ring[];
    float* shred = (float*)ring;             // aliased reduction scratch

    const int tid = threadIdx.x;
    const int blk = blockIdx.x;

    const float th0 = theta[0];
    const float th1 = theta[1];
    const float th2 = theta[2];
    const float sdev = sdevp[0];

    const float kk = __fmul_rn(-2.0f, th1);   // reference rounding (validated)
    const float gf = 2.0f * th1;

    const ull sd2   = SPL(sdev);
    // log2e folded into Metropolis constant: z = lkz*xp^2 + nhz, nhz = -lkz*xs^2
    const float lkzf = kk * 1.44269504f;
    const ull lkz2  = SPL(lkzf);
    const ull nlkz2 = SPL(-lkzf);

    // 2^f poly on f in [-0.5, 0.5] (deg-5), magic rounding -- identical to R6
    const ull magic = SPL(12582912.0f);
    const ull nmag  = SPL(-12582912.0f);
    const ull mone  = SPL(-1.0f);
    const ull e5 = SPL(1.33335581e-3f), e4 = SPL(9.61812910e-3f);
    const ull e3 = SPL(5.55041086e-2f), e2 = SPL(2.40226507e-1f);
    const ull e1 = SPL(6.93147182e-1f), e0 = SPL(1.0f);

    // Energy polys in t = xs^2, coeffs folded in fp64 once
    const double dth0 = (double)th0, dth1 = (double)th1;
    const double dg = 2.0 * dth1, g2d = dg * dg;
    const double dC1 = -2.0 * exp(-dth1) * cos(dth0);
    const double dC2 =  2.0 * exp(-dth1) * sin(dth0);
    const ull A0 = SPL((float)dC1);
    const ull A1 = SPL((float)(dC1 * g2d / 2.0));
    const ull A2 = SPL((float)(dC1 * g2d * g2d / 24.0));
    const ull A3 = SPL((float)(dC1 * g2d * g2d * g2d / 720.0));
    const ull B0 = SPL((float)(dC2 * dg));
    const ull B1 = SPL((float)(dC2 * dg * g2d / 6.0));
    const ull B2 = SPL((float)(dC2 * dg * g2d * g2d / 120.0));

    // ---- two independent chains: pairs A = blk*256+tid, B = +128 ----
    const float2 rA = ((const float2*)r0)[blk * PPB + tid];
    const float2 rB = ((const float2*)r0)[blk * PPB + 128 + tid];
    ull xsA  = PKF(__fsub_rn(rA.x, th2), __fsub_rn(rA.y, th2));
    ull xsB  = PKF(__fsub_rn(rB.x, th2), __fsub_rn(rB.y, th2));
    ull xs2A = MUL2(xsA, xsA), xs2B = MUL2(xsB, xsB);
    ull nhzA = MUL2(nlkz2, xs2A), nhzB = MUL2(nlkz2, xs2B);

    // ---- cp.async geometry: row = 256 pairs = 2048 B = 128 granules ----
    const uint32_t base = (uint32_t)__cvta_generic_to_shared(ring);
    const size_t sliceOff = (size_t)blk * 2048 + (size_t)tid * 16;
    const char* gN = (const char*)noise + sliceOff;
    const char* gU = (const char*)unif  + sliceOff;

#define ISSUE_CHUNK(s0, stg) do {                                            \
        const char* _n = gN + (size_t)(s0) * ROWB;                           \
        const char* _u = gU + (size_t)(s0) * ROWB;                           \
        uint32_t _sb = base + (uint32_t)(stg) * (STG * 8);                   \
        _Pragma("unroll")                                                    \
        for (int _r = 0; _r < CH; _r++) {                                    \
            uint32_t _d = (uint32_t)(_r * 2048 + tid * 16);                  \
            cp16(_sb + _d,            _n + (size_t)_r * ROWB);               \
            cp16(_sb + UOFF * 8 + _d, _u + (size_t)_r * ROWB);               \
        }                                                                    \
        asm volatile("cp.async.commit_group;" ::: "memory");                 \
    } while (0)

    // Metropolis step; decisions bit-identical to R6. Updates XS, XS2, NHZ.
#define METRO(n, u, XS, XS2, NHZ) do {                                       \
        ull sn  = MUL2(sd2, (n));                                            \
        ull xp  = ADD2(XS, sn);                                              \
        ull xp2 = MUL2(xp, xp);                                              \
        ull z   = FMA2(lkz2, xp2, NHZ);                                      \
        ull fz  = ADD2(z, magic);                                            \
        ull kf  = ADD2(fz, nmag);                                            \
        ull f   = FMA2(kf, mone, z);                                         \
        ull p   = FMA2(e5, f, e4);                                           \
        p = FMA2(p, f, e3); p = FMA2(p, f, e2);                              \
        p = FMA2(p, f, e1); p = FMA2(p, f, e0);                              \
        unsigned eplo = (unsigned)p        + (((unsigned)fz        - 0x4B400000u) << 23); \
        unsigned ephi = (unsigned)(p >> 32) + (((unsigned)(fz >> 32) - 0x4B400000u) << 23); \
        bool aLo = ((unsigned)(u)         < eplo);                           \
        bool aHi = ((unsigned)((u) >> 32) < ephi);                           \
        unsigned xs_lo  = aLo ? (unsigned)xp         : (unsigned)XS;         \
        unsigned xs_hi  = aHi ? (unsigned)(xp  >> 32) : (unsigned)(XS  >> 32); \
        unsigned x2_lo  = aLo ? (unsigned)xp2        : (unsigned)XS2;        \
        unsigned x2_hi  = aHi ? (unsigned)(xp2 >> 32) : (unsigned)(XS2 >> 32); \
        XS  = PKU(xs_lo, xs_hi);                                             \
        XS2 = PKU(x2_lo, x2_hi);                                             \
        NHZ = MUL2(nlkz2, XS2);   /* == selected -lkz*xp2 bit-exactly */     \
    } while (0)

#define MEAS(XS, XS2) do {                                                   \
        ull t  = XS2;                                                        \
        ull er = FMA2(A3, t, A2);                                            \
        er = FMA2(er, t, A1); er = FMA2(er, t, A0);                          \
        ull pb = FMA2(B2, t, B1);                                            \
        pb = FMA2(pb, t, B0);                                                \
        ull ei = MUL2(XS, pb);                                               \
        S0 = ADD2(S0, er);                                                   \
        S1 = ADD2(S1, ei);                                                   \
        S2 = ADD2(S2, XS);                                                   \
        S3 = ADD2(S3, t);                                                    \
        S4 = FMA2(XS, er, S4);                                               \
        S5 = FMA2(XS, ei, S5);                                               \
        S6 = FMA2(t,  er, S6);                                               \
        S7 = FMA2(t,  ei, S7);                                               \
    } while (0)

    ull S0 = 0, S1 = 0, S2 = 0, S3 = 0, S4 = 0, S5 = 0, S6 = 0, S7 = 0;

    ISSUE_CHUNK(0 * CH, 0);
    ISSUE_CHUNK(1 * CH, 1);
    ISSUE_CHUNK(2 * CH, 2);

    for (int c = 0; c < NCH; c++) {
        asm volatile("cp.async.wait_group 2;" ::: "memory");
        __syncthreads();

        if (c + 3 < NCH) {
            ISSUE_CHUNK((c + 3) * CH, (c + 3) & 3);
        } else {
            asm volatile("cp.async.commit_group;" ::: "memory");
        }

        const ull* st = ring + (size_t)(c & 3) * STG;

        // ---- chunk-front hoist: all LDS for this chunk issue back-to-back ----
        ull nA[CH], uA[CH], nB[CH], uB[CH];
#pragma unroll
        for (int j = 0; j < CH; j++) {
            nA[j] = st[j * PPB + tid];
            uA[j] = st[UOFF + j * PPB + tid];
            nB[j] = st[j * PPB + 128 + tid];
            uB[j] = st[UOFF + j * PPB + 128 + tid];
        }

        if (c < WARM_CH) {
#pragma unroll
            for (int j = 0; j < CH; j++) {
                METRO(nA[j], uA[j], xsA, xs2A, nhzA);
                METRO(nB[j], uB[j], xsB, xs2B, nhzB);
            }
        } else {
#pragma unroll
            for (int j = 0; j < CH; j++) {
                METRO(nA[j], uA[j], xsA, xs2A, nhzA);
                METRO(nB[j], uB[j], xsB, xs2B, nhzB);
                MEAS(xsA, xs2A);
                MEAS(xsB, xs2B);
            }
        }
    }

    // ---------------- block reduction (4 warps) ----------------
    float v0 = LO(S0) + HI(S0), v1 = LO(S1) + HI(S1);
    float v2 = LO(S2) + HI(S2), v3 = LO(S3) + HI(S3);
    float v4 = LO(S4) + HI(S4), v5 = LO(S5) + HI(S5);
    float v6 = LO(S6) + HI(S6), v7 = LO(S7) + HI(S7);

    const unsigned m = 0xffffffffu;
#pragma unroll
    for (int o = 16; o; o >>= 1) {
        v0 += __shfl_xor_sync(m, v0, o);
        v1 += __shfl_xor_sync(m, v1, o);
        v2 += __shfl_xor_sync(m, v2, o);
        v3 += __shfl_xor_sync(m, v3, o);
        v4 += __shfl_xor_sync(m, v4, o);
        v5 += __shfl_xor_sync(m, v5, o);
        v6 += __shfl_xor_sync(m, v6, o);
        v7 += __shfl_xor_sync(m, v7, o);
    }

    float* sh   = shred;            // [8][4]
    float* s8   = shred + 32;       // [8]
    int*  sLast = (int*)(shred + 40);

    __syncthreads();                // ring reads done before aliasing
    const int lane = tid & 31;
    const int wp   = tid >> 5;      // 4 warps
    if (lane == 0) {
        sh[0 * 4 + wp] = v0; sh[1 * 4 + wp] = v1;
        sh[2 * 4 + wp] = v2; sh[3 * 4 + wp] = v3;
        sh[4 * 4 + wp] = v4; sh[5 * 4 + wp] = v5;
        sh[6 * 4 + wp] = v6; sh[7 * 4 + wp] = v7;
    }
    __syncthreads();
    if (tid < 32) {
        const int q  = tid >> 2;
        const int wj = tid & 3;
        float v = sh[q * 4 + wj];
        v += __shfl_down_sync(m, v, 2, 4);
        v += __shfl_down_sync(m, v, 1, 4);
        if (wj == 0) g_part[q][blk] = v;
    }
    __threadfence();
    __syncthreads();
    if (tid == 0) {
        unsigned old = atomicAdd(&g_ctr, 1u);
        *sLast = ((old % NBLK) == (NBLK - 1)) ? 1 : 0;
    }
    __syncthreads();

    // ---------------- last block: final reduce + output ----------------
    if (*sLast) {
        const int q = tid >> 4;     // 8 quantities x 16 lanes
        const int l = tid & 15;
        float v = 0.f;
#pragma unroll
        for (int i = l; i < NBLK; i += 16) v += __ldcg(&g_part[q][i]);
#pragma unroll
        for (int o = 8; o; o >>= 1) v += __shfl_down_sync(m, v, o, 16);
        if (l == 0) s8[q] = v;
        __syncthreads();

        if (tid == 0) {
            const float inv = 1.0f / ((float)NW * (float)NSTEPS);
            const float Ser   = s8[0] * inv;
            const float Sei   = s8[1] * inv;
            const float Sxs   = s8[2] * inv;   // mean(r) - th2
            const float Sx2   = s8[3] * inv;
            const float Sxer  = s8[4] * inv;
            const float Sxei  = s8[5] * inv;
            const float Sx2er = s8[6] * inv;
            const float Sx2ei = s8[7] * inv;

            if (out_size == 14) {
                const float Sr   = Sxs + th2;
                const float Srer = Sxer + th2 * Ser;
                const float Srei = Sxei + th2 * Sei;
                float2* o2 = (float2*)out;
                o2[0] = make_float2(Ser, Sei);
                o2[1] = make_float2(0.0f, Sr);
                o2[2] = make_float2(Sx2, 0.0f);
                o2[3] = make_float2(gf * Sxs, 0.0f);
                o2[4] = make_float2(Srei, -Srer);
                o2[5] = make_float2(Sx2er, Sx2ei);
                o2[6] = make_float2(gf * Sxer, gf * Sxei);
            } else {
                out[0] = Ser;                  // Es.re
                out[1] = 0.0f;                 // Ds0.re
                out[2] = Sx2;                  // Ds1.re
                out[3] = gf * Sxs;             // Ds2.re
                out[4] = Sxei + th2 * Sei;     // EDs0.re
                out[5] = Sx2er;                // EDs1.re
                out[6] = gf * Sxer;            // EDs2.re
            }
        }
    }
}

extern "C" void kernel_launch(void* const* d_in, const int* in_sizes, int n_in,
                              void* d_out, int out_size)
{
    const float* theta = (const float*)d_in[0];
    const float* r0    = (const float*)d_in[1];
    const float* sdev  = (const float*)d_in[2];
    const float* noise = (const float*)d_in[3];
    const float* unif  = (const float*)d_in[4];

    cudaFuncSetAttribute(vmc_kernel, cudaFuncAttributeMaxDynamicSharedMemorySize,
                         SMEM_BYTES);

    vmc_kernel<<<NBLK, TPB, SMEM_BYTES>>>(theta, r0, sdev, noise, unif,
                                          (float*)d_out, out_size);
}